// round 9
// baseline (speedup 1.0000x reference)
#include <cuda_runtime.h>
#include <cuda_fp16.h>
#include <cuda_bf16.h>

#define N_NODES 100000
#define N_EDGES 1600000
#define TOT (N_EDGES + N_NODES)
#define NB_SCAN ((N_NODES + 1023) / 1024)   // 98

// ---------------- scratch -----------------------------------------------------
__device__ int    g_deg[N_NODES];
__device__ int    g_incl[N_NODES];
__device__ int    g_bsum[128];
__device__ int    g_rowptr[N_NODES + 1];
__device__ int    g_cursor[N_NODES];
__device__ int2   g_cw[TOT];             // {src*64, __float_as_int(dinv[src])}
__device__ float  g_dinv[N_NODES];
__device__ int    g_is64;

__device__ __align__(256) __half g_M[N_NODES * 64];   // fp16 message buffer
__device__ float g_XT[N_NODES * 64];                  // x_temp residual (fp32)
__device__ float g_h1[N_NODES * 64];                  // hidden (fp32)

// ---------------- helpers ------------------------------------------------------
__device__ __forceinline__ int load_idx(const void* ei, int pos) {
    if (g_is64) return (int)((const long long*)ei)[pos];
    return ((const int*)ei)[pos];
}

__global__ void k_init(const void* ei) {
    int i = blockIdx.x * blockDim.x + threadIdx.x;
    if (i < N_NODES) g_deg[i] = 1;
    if (i == 0) {
        const long long* p = (const long long*)ei;
        int ok64 = 1;
        #pragma unroll
        for (int j = 0; j < 16; j++) {
            long long v = p[j];
            if (v < 0 || v >= N_NODES) ok64 = 0;
        }
        g_is64 = ok64;
    }
}

__global__ void k_count(const void* ei) {
    int t = blockIdx.x * blockDim.x + threadIdx.x;
    if (t < N_EDGES) atomicAdd(&g_deg[load_idx(ei, N_EDGES + t)], 1);
}

__global__ void k_scan1() {
    __shared__ int s[1024];
    int tid = threadIdx.x;
    int i = blockIdx.x * 1024 + tid;
    int v = (i < N_NODES) ? g_deg[i] : 0;
    s[tid] = v;
    __syncthreads();
    #pragma unroll
    for (int off = 1; off < 1024; off <<= 1) {
        int t = (tid >= off) ? s[tid - off] : 0;
        __syncthreads();
        s[tid] += t;
        __syncthreads();
    }
    if (i < N_NODES) g_incl[i] = s[tid];
    if (tid == 1023) g_bsum[blockIdx.x] = s[1023];
}

__global__ void k_scan2f() {
    __shared__ int sb[128];
    int tid = threadIdx.x;
    if (tid < 128) sb[tid] = (tid < NB_SCAN) ? g_bsum[tid] : 0;
    __syncthreads();
    int boff = 0;
    for (int j = 0; j < (int)blockIdx.x; j++) boff += sb[j];
    int i = blockIdx.x * 1024 + tid;
    if (i < N_NODES) {
        int rp = g_incl[i] - g_deg[i] + boff;
        g_rowptr[i] = rp;
        g_cursor[i] = rp;
        g_dinv[i]   = rsqrtf((float)g_deg[i]);
    }
    if (i == 0) g_rowptr[N_NODES] = TOT;
}

__global__ void k_fill(const void* ei) {
    int t = blockIdx.x * blockDim.x + threadIdx.x;
    if (t < N_EDGES) {
        int s = load_idx(ei, t);
        int d = load_idx(ei, N_EDGES + t);
        int pos = atomicAdd(&g_cursor[d], 1);
        g_cw[pos] = make_int2(s * 64, __float_as_int(g_dinv[s]));
    } else if (t < TOT) {
        int i = t - N_EDGES;
        int pos = atomicAdd(&g_cursor[i], 1);
        g_cw[pos] = make_int2(i * 64, __float_as_int(g_dinv[i]));
    }
}

// ---------------- tiled GEMM: M16 = [dinv *] (X @ W),  fp16 out ---------------
template <int K, bool SCALE>
__global__ void __launch_bounds__(256) k_gemm(const float* __restrict__ X,
                                              const float* __restrict__ W,
                                              __half* __restrict__ M) {
    __shared__ float As[32][132];
    __shared__ float Bs[32][64];
    int tid = threadIdx.x;
    int block_row = blockIdx.x * 128;
    int txc = tid & 7;
    int tyr = tid >> 3;

    int lrow = tid >> 1;
    int kh   = (tid & 1) * 16;
    int lkB  = tid >> 3;
    int lcB  = (tid & 7) * 8;

    float acc[4][8];
    #pragma unroll
    for (int i = 0; i < 4; i++)
        #pragma unroll
        for (int j = 0; j < 8; j++) acc[i][j] = 0.f;

    for (int k0 = 0; k0 < K; k0 += 32) {
        int grow = block_row + lrow;
        #pragma unroll
        for (int j = 0; j < 4; j++) {
            int ko = kh + j * 4;
            float4 v = make_float4(0.f, 0.f, 0.f, 0.f);
            if (grow < N_NODES) v = *(const float4*)&X[(size_t)grow * K + k0 + ko];
            As[ko + 0][lrow] = v.x;
            As[ko + 1][lrow] = v.y;
            As[ko + 2][lrow] = v.z;
            As[ko + 3][lrow] = v.w;
        }
        *(float4*)&Bs[lkB][lcB]     = *(const float4*)&W[(size_t)(k0 + lkB) * 64 + lcB];
        *(float4*)&Bs[lkB][lcB + 4] = *(const float4*)&W[(size_t)(k0 + lkB) * 64 + lcB + 4];
        __syncthreads();

        #pragma unroll 8
        for (int kk = 0; kk < 32; kk++) {
            float4 a  = *(const float4*)&As[kk][tyr * 4];
            float4 b0 = *(const float4*)&Bs[kk][txc * 8];
            float4 b1 = *(const float4*)&Bs[kk][txc * 8 + 4];
            float av[4] = {a.x, a.y, a.z, a.w};
            float bv[8] = {b0.x, b0.y, b0.z, b0.w, b1.x, b1.y, b1.z, b1.w};
            #pragma unroll
            for (int i = 0; i < 4; i++)
                #pragma unroll
                for (int j = 0; j < 8; j++)
                    acc[i][j] = fmaf(av[i], bv[j], acc[i][j]);
        }
        __syncthreads();
    }

    #pragma unroll
    for (int i = 0; i < 4; i++) {
        int gr = block_row + tyr * 4 + i;
        if (gr < N_NODES) {
            float di = SCALE ? g_dinv[gr] : 1.f;
            __half2 h[4];
            #pragma unroll
            for (int j = 0; j < 4; j++)
                h[j] = __floats2half2_rn(acc[i][2 * j] * di, acc[i][2 * j + 1] * di);
            uint4 pack;
            pack.x = *(unsigned*)&h[0];
            pack.y = *(unsigned*)&h[1];
            pack.z = *(unsigned*)&h[2];
            pack.w = *(unsigned*)&h[3];
            *(uint4*)&M[(size_t)gr * 64 + txc * 8] = pack;
        }
    }
}

// ---------------- quarter-warp fp16 aggregate ---------------------------------
// warp-per-node; 4 groups of 8 lanes, each group handles one edge per step,
// each lane loads uint4 = 8 halves (its 8 channels). 8 LDG.128 per edge.
template <bool WEIGHTED, bool RELU, bool ADDRES>
__global__ void __launch_bounds__(512) k_agg(const __half* __restrict__ M,
                                             const float* __restrict__ bias,
                                             const float* __restrict__ res,
                                             float* __restrict__ outp) {
    int lane = threadIdx.x & 31;
    int qid  = lane >> 3;          // 0..3: edge slot within step
    int ql8  = (lane & 7) * 8;     // channel offset (8 channels per lane)
    int row  = (blockIdx.x * 512 + threadIdx.x) >> 5;
    if (row >= N_NODES) return;

    int s  = g_rowptr[row];
    int en = g_rowptr[row + 1];
    float a0 = 0.f, a1 = 0.f, a2 = 0.f, a3 = 0.f;
    float a4 = 0.f, a5 = 0.f, a6 = 0.f, a7 = 0.f;
    int e = s;

    #pragma unroll 1
    for (; e + 8 <= en; e += 8) {
        int2 cwA = g_cw[e + qid];
        int2 cwB = g_cw[e + 4 + qid];
        uint4 hA = *(const uint4*)&M[cwA.x + ql8];
        uint4 hB = *(const uint4*)&M[cwB.x + ql8];
        float2 fA0 = __half22float2(*(__half2*)&hA.x);
        float2 fA1 = __half22float2(*(__half2*)&hA.y);
        float2 fA2 = __half22float2(*(__half2*)&hA.z);
        float2 fA3 = __half22float2(*(__half2*)&hA.w);
        float2 fB0 = __half22float2(*(__half2*)&hB.x);
        float2 fB1 = __half22float2(*(__half2*)&hB.y);
        float2 fB2 = __half22float2(*(__half2*)&hB.z);
        float2 fB3 = __half22float2(*(__half2*)&hB.w);
        if (WEIGHTED) {
            float wA = __int_as_float(cwA.y);
            float wB = __int_as_float(cwB.y);
            a0 = fmaf(fA0.x, wA, a0); a1 = fmaf(fA0.y, wA, a1);
            a2 = fmaf(fA1.x, wA, a2); a3 = fmaf(fA1.y, wA, a3);
            a4 = fmaf(fA2.x, wA, a4); a5 = fmaf(fA2.y, wA, a5);
            a6 = fmaf(fA3.x, wA, a6); a7 = fmaf(fA3.y, wA, a7);
            a0 = fmaf(fB0.x, wB, a0); a1 = fmaf(fB0.y, wB, a1);
            a2 = fmaf(fB1.x, wB, a2); a3 = fmaf(fB1.y, wB, a3);
            a4 = fmaf(fB2.x, wB, a4); a5 = fmaf(fB2.y, wB, a5);
            a6 = fmaf(fB3.x, wB, a6); a7 = fmaf(fB3.y, wB, a7);
        } else {
            a0 += fA0.x + fB0.x; a1 += fA0.y + fB0.y;
            a2 += fA1.x + fB1.x; a3 += fA1.y + fB1.y;
            a4 += fA2.x + fB2.x; a5 += fA2.y + fB2.y;
            a6 += fA3.x + fB3.x; a7 += fA3.y + fB3.y;
        }
    }
    for (; e + 4 <= en; e += 4) {
        int2 cw = g_cw[e + qid];
        uint4 hv = *(const uint4*)&M[cw.x + ql8];
        float2 f0 = __half22float2(*(__half2*)&hv.x);
        float2 f1 = __half22float2(*(__half2*)&hv.y);
        float2 f2 = __half22float2(*(__half2*)&hv.z);
        float2 f3 = __half22float2(*(__half2*)&hv.w);
        float w = WEIGHTED ? __int_as_float(cw.y) : 1.f;
        a0 = fmaf(f0.x, w, a0); a1 = fmaf(f0.y, w, a1);
        a2 = fmaf(f1.x, w, a2); a3 = fmaf(f1.y, w, a3);
        a4 = fmaf(f2.x, w, a4); a5 = fmaf(f2.y, w, a5);
        a6 = fmaf(f3.x, w, a6); a7 = fmaf(f3.y, w, a7);
    }
    if (e + qid < en) {
        int2 cw = g_cw[e + qid];
        uint4 hv = *(const uint4*)&M[cw.x + ql8];
        float2 f0 = __half22float2(*(__half2*)&hv.x);
        float2 f1 = __half22float2(*(__half2*)&hv.y);
        float2 f2 = __half22float2(*(__half2*)&hv.z);
        float2 f3 = __half22float2(*(__half2*)&hv.w);
        float w = WEIGHTED ? __int_as_float(cw.y) : 1.f;
        a0 = fmaf(f0.x, w, a0); a1 = fmaf(f0.y, w, a1);
        a2 = fmaf(f1.x, w, a2); a3 = fmaf(f1.y, w, a3);
        a4 = fmaf(f2.x, w, a4); a5 = fmaf(f2.y, w, a5);
        a6 = fmaf(f3.x, w, a6); a7 = fmaf(f3.y, w, a7);
    }

    // reduce across the 4 quarter-groups (lanes with equal lane&7)
    #pragma unroll
    for (int off = 8; off <= 16; off <<= 1) {
        a0 += __shfl_xor_sync(0xffffffffu, a0, off);
        a1 += __shfl_xor_sync(0xffffffffu, a1, off);
        a2 += __shfl_xor_sync(0xffffffffu, a2, off);
        a3 += __shfl_xor_sync(0xffffffffu, a3, off);
        a4 += __shfl_xor_sync(0xffffffffu, a4, off);
        a5 += __shfl_xor_sync(0xffffffffu, a5, off);
        a6 += __shfl_xor_sync(0xffffffffu, a6, off);
        a7 += __shfl_xor_sync(0xffffffffu, a7, off);
    }

    if (lane < 8) {
        float di = g_dinv[row];
        float4 b0 = *(const float4*)&bias[ql8];
        float4 b1 = *(const float4*)&bias[ql8 + 4];
        float o0 = fmaf(a0, di, b0.x);
        float o1 = fmaf(a1, di, b0.y);
        float o2 = fmaf(a2, di, b0.z);
        float o3 = fmaf(a3, di, b0.w);
        float o4 = fmaf(a4, di, b1.x);
        float o5 = fmaf(a5, di, b1.y);
        float o6 = fmaf(a6, di, b1.z);
        float o7 = fmaf(a7, di, b1.w);
        if (RELU) {
            o0 = fmaxf(o0, 0.f); o1 = fmaxf(o1, 0.f);
            o2 = fmaxf(o2, 0.f); o3 = fmaxf(o3, 0.f);
            o4 = fmaxf(o4, 0.f); o5 = fmaxf(o5, 0.f);
            o6 = fmaxf(o6, 0.f); o7 = fmaxf(o7, 0.f);
        }
        if (ADDRES) {
            float4 r0 = *(const float4*)&res[(size_t)row * 64 + ql8];
            float4 r1 = *(const float4*)&res[(size_t)row * 64 + ql8 + 4];
            o0 += r0.x; o1 += r0.y; o2 += r0.z; o3 += r0.w;
            o4 += r1.x; o5 += r1.y; o6 += r1.z; o7 += r1.w;
        }
        *(float4*)&outp[(size_t)row * 64 + ql8]     = make_float4(o0, o1, o2, o3);
        *(float4*)&outp[(size_t)row * 64 + ql8 + 4] = make_float4(o4, o5, o6, o7);
    }
}

// ---------------- launch --------------------------------------------------------
extern "C" void kernel_launch(void* const* d_in, const int* in_sizes, int n_in,
                              void* d_out, int out_size) {
    const float* x  = (const float*)d_in[0];
    const void*  ei = d_in[1];
    const float* W0 = (const float*)d_in[2];
    const float* b0 = (const float*)d_in[3];
    const float* Ws = (const float*)d_in[4];
    const float* bs = (const float*)d_in[5];
    float* out = (float*)d_out;

    const float* Ws0 = Ws;
    const float* Ws1 = Ws + 64 * 64;
    const float* bs0 = bs;
    const float* bs1 = bs + 64;

    __half* M = nullptr;
    float *XT = nullptr, *H1 = nullptr;
    cudaGetSymbolAddress((void**)&M,  g_M);
    cudaGetSymbolAddress((void**)&XT, g_XT);
    cudaGetSymbolAddress((void**)&H1, g_h1);

    static cudaStream_t s2 = nullptr;
    static cudaEvent_t evF = nullptr, evG = nullptr;
    if (s2 == nullptr) {
        cudaStreamCreateWithFlags(&s2, cudaStreamNonBlocking);
        cudaEventCreateWithFlags(&evF, cudaEventDisableTiming);
        cudaEventCreateWithFlags(&evG, cudaEventDisableTiming);
    }

    const int GEMM_BLOCKS = (N_NODES + 127) / 128;           // 782
    const int AGG_BLOCKS  = (N_NODES * 32 + 511) / 512;      // 6250

    // ---- fork: gemm0 (independent of graph build) on side stream ----
    cudaEventRecord(evF, 0);
    cudaStreamWaitEvent(s2, evF, 0);
    k_gemm<128, false><<<GEMM_BLOCKS, 256, 0, s2>>>(x, W0, M);  // M = fp16(x@W0)
    cudaEventRecord(evG, s2);

    // ---- CSR build on default stream (concurrent with gemm0) ----
    k_init<<<(N_NODES + 255) / 256, 256>>>(ei);
    k_count<<<(N_EDGES + 511) / 512, 512>>>(ei);
    k_scan1<<<NB_SCAN, 1024>>>();
    k_scan2f<<<NB_SCAN, 1024>>>();
    k_fill<<<(TOT + 511) / 512, 512>>>(ei);

    // ---- join, then the serial conv chain ----
    cudaStreamWaitEvent(0, evG, 0);
    // layer 0: XT = agg_w(M) + b0   (per-edge dinv[src] weights)
    k_agg<true, false, false><<<AGG_BLOCKS, 512>>>(M, b0, nullptr, XT);
    // layer 1: M = fp16(dinv*(XT@Ws0)); h1 = relu(agg(M)+bs0)
    k_gemm<64, true><<<GEMM_BLOCKS, 256>>>(XT, Ws0, M);
    k_agg<false, true, false><<<AGG_BLOCKS, 512>>>(M, bs0, nullptr, H1);
    // layer 2: M = fp16(dinv*(h1@Ws1)); out = relu(agg(M)+bs1) + XT
    k_gemm<64, true><<<GEMM_BLOCKS, 256>>>(H1, Ws1, M);
    k_agg<false, true, true><<<AGG_BLOCKS, 512>>>(M, bs1, XT, out);
}